// round 3
// baseline (speedup 1.0000x reference)
#include <cuda_runtime.h>
#include <cuda_bf16.h>
#include <cstdint>

// LSTM decoder: B=1024, H=128, O=7, T=512.
// gates = h @ (W_ih+W_hh)^T + (b_ih+b_hh)   (reference uses h for both matmuls)
// Persistent kernel: 128 blocks x 128 threads, each block owns 8 batch rows.
// Inner product in packed fp32x2 (fma.rn.f32x2), k-pair dot accumulation.
// Gates i,f,g weights in SMEM; o-gate weights streamed from L2 with a
// software-pipelined (one-group-ahead) register prefetch.

#define B_TOTAL   1024
#define HID       128
#define GATES     512          // 4*HID
#define T_STEPS   512
#define OUT_DIM   7
#define ROWS      8            // batch rows per block
#define NBLOCKS   (B_TOTAL / ROWS)   // 128
#define TPB       128

// __device__ scratch (allowed; no cudaMalloc): combined transposed weights + bias
// g_W layout: float4[k4][g], k4 = k/4 in 0..31, g in 0..511; float4 = W[g][4k4..4k4+3]
__device__ float4 g_W[32 * GATES];        // 256 KB
__device__ float  g_bias[GATES];          // 2 KB

// ---------- helpers ----------
__device__ __forceinline__ void ffma2(unsigned long long& d,
                                      unsigned long long a,
                                      unsigned long long b) {
    asm("fma.rn.f32x2 %0, %1, %2, %0;" : "+l"(d) : "l"(a), "l"(b));
}
__device__ __forceinline__ float pairsum(unsigned long long v) {
    float a, b;
    asm("mov.b64 {%0, %1}, %2;" : "=f"(a), "=f"(b) : "l"(v));
    return a + b;
}
__device__ __forceinline__ float sigf(float x) {
    return __fdividef(1.0f, 1.0f + __expf(-x));
}
__device__ __forceinline__ float tanh_fast(float x) {
    // tanh(x) = 2/(1+e^{-2x}) - 1 ; saturates correctly at +-inf
    return __fdividef(2.0f, 1.0f + __expf(-2.0f * x)) - 1.0f;
}

// ---------- prep: combine + transpose weights, combine bias ----------
__global__ void prep_kernel(const float* __restrict__ Wih,
                            const float* __restrict__ Whh,
                            const float* __restrict__ bih,
                            const float* __restrict__ bhh) {
    int idx = blockIdx.x * blockDim.x + threadIdx.x;   // 0..16383
    if (idx < 32 * GATES) {
        int g  = idx & (GATES - 1);
        int k4 = idx >> 9;
        int base = g * HID + k4 * 4;
        float4 v;
        v.x = Wih[base + 0] + Whh[base + 0];
        v.y = Wih[base + 1] + Whh[base + 1];
        v.z = Wih[base + 2] + Whh[base + 2];
        v.w = Wih[base + 3] + Whh[base + 3];
        g_W[k4 * GATES + g] = v;
    }
    if (idx < GATES) g_bias[idx] = bih[idx] + bhh[idx];
}

// ---------- main persistent LSTM kernel ----------
// smem: s_w   float4[32][384]  (gates i,f,g)      = 196608 B
//       s_h   float[2][8][128] (double-buffered h)=   8192 B
//       s_wout float4[7][33]   (padded W_out)     =   3696 B
#define SW_F4      (32 * 384)          // 12288 float4
#define SH_OFF_F   (SW_F4 * 4)         // float offset 49152
#define SWOUT_OFF_F (SH_OFF_F + 2 * ROWS * HID)   // 49152 + 2048 = 51200
#define SMEM_BYTES ((SWOUT_OFF_F * 4) + OUT_DIM * 33 * 16)   // 204800 + 3696 = 208496

__global__ void __launch_bounds__(TPB, 1)
lstm_kernel(const float* __restrict__ ctx,
            const float* __restrict__ Wout,
            const float* __restrict__ bout,
            float* __restrict__ out) {
    extern __shared__ float smem[];
    float4* s_w    = reinterpret_cast<float4*>(smem);
    float*  s_h    = smem + SH_OFF_F;
    float4* s_wout = reinterpret_cast<float4*>(smem + SWOUT_OFF_F);

    const int t   = threadIdx.x;   // hidden-unit index (0..127)
    const int blk = blockIdx.x;

    // stage W (gates i,f,g) into shared: s_w[k4*384 + g], g<384
    for (int i = t; i < SW_F4; i += TPB) {
        int k4 = i / 384;
        int g  = i - k4 * 384;
        s_w[i] = g_W[k4 * GATES + g];
    }
    // stage W_out with padded pitch 33 float4
    const float4* Wout4 = reinterpret_cast<const float4*>(Wout);
    for (int i = t; i < OUT_DIM * 32; i += TPB) {
        int o = i / 32, kk = i - o * 32;
        s_wout[o * 33 + kk] = Wout4[o * 32 + kk];
    }
    // h0 = ctx[b][255][:]
    for (int r = 0; r < ROWS; r++) {
        int b = blk * ROWS + r;
        s_h[r * HID + t] = ctx[((size_t)b * 256 + 255) * HID + t];
    }
    // per-thread biases (4 gates of unit t)
    const float bi = g_bias[t];
    const float bf = g_bias[HID + t];
    const float bg = g_bias[2 * HID + t];
    const float bo = g_bias[3 * HID + t];

    // o-gate weight rows live in L2 (don't fit in SMEM); coalesced per k4.
    // row pitch between consecutive k4 is GATES ulonglong2.
    const ulonglong2* __restrict__ wO = reinterpret_cast<const ulonglong2*>(&g_W[3 * HID + t]);

    // pred mapping: 56 threads spread over all warps
    const int pr = t >> 4;          // row 0..7
    const int po = t & 15;          // out idx, active if < 7
    const float bpred = (po < OUT_DIM) ? bout[po] : 0.0f;
    float* out_base = out + ((size_t)(blk * ROWS + pr) * T_STEPS) * OUT_DIM + po;

    float c[ROWS];
#pragma unroll
    for (int r = 0; r < ROWS; r++) c[r] = 0.0f;

    __syncthreads();

    int cur = 0;
    for (int s = 0; s < T_STEPS; s++) {
        const float* hc = s_h + cur * (ROWS * HID);
        float*       hn = s_h + (cur ^ 1) * (ROWS * HID);

        unsigned long long a0[ROWS], a1[ROWS], a2[ROWS], a3[ROWS];
#pragma unroll
        for (int r = 0; r < ROWS; r++) { a0[r] = 0ull; a1[r] = 0ull; a2[r] = 0ull; a3[r] = 0ull; }

        // ---- o-gate prefetch pipeline: group of 4 k4-rows ahead ----
        ulonglong2 w3buf[4];
#pragma unroll
        for (int j = 0; j < 4; j++) w3buf[j] = __ldg(&wO[(size_t)j * GATES]);

#pragma unroll 4
        for (int k4 = 0; k4 < 32; k4++) {
            ulonglong2 w0 = *reinterpret_cast<const ulonglong2*>(&s_w[k4 * 384 + t]);
            ulonglong2 w1 = *reinterpret_cast<const ulonglong2*>(&s_w[k4 * 384 + HID + t]);
            ulonglong2 w2 = *reinterpret_cast<const ulonglong2*>(&s_w[k4 * 384 + 2 * HID + t]);
            ulonglong2 w3 = w3buf[k4 & 3];
            if ((k4 & 3) == 3 && k4 + 1 < 32) {
                // refill next group of 4 (stays >= 4 LDGs in flight)
#pragma unroll
                for (int j = 0; j < 4; j++)
                    w3buf[j] = __ldg(&wO[(size_t)(k4 + 1 + j) * GATES]);
            }
#pragma unroll
            for (int r = 0; r < ROWS; r++) {
                ulonglong2 h2 = *reinterpret_cast<const ulonglong2*>(hc + r * HID + k4 * 4); // broadcast
                ffma2(a0[r], h2.x, w0.x); ffma2(a0[r], h2.y, w0.y);
                ffma2(a1[r], h2.x, w1.x); ffma2(a1[r], h2.y, w1.y);
                ffma2(a2[r], h2.x, w2.x); ffma2(a2[r], h2.y, w2.y);
                ffma2(a3[r], h2.x, w3.x); ffma2(a3[r], h2.y, w3.y);
            }
        }

        // LSTM elementwise (all state thread-local), write h_new to other buffer
#pragma unroll
        for (int r = 0; r < ROWS; r++) {
            float gi = pairsum(a0[r]) + bi;
            float gf = pairsum(a1[r]) + bf;
            float gg = pairsum(a2[r]) + bg;
            float go = pairsum(a3[r]) + bo;
            float iv = sigf(gi);
            float fv = sigf(gf);
            float gv = tanh_fast(gg);
            float ov = sigf(go);
            c[r] = fv * c[r] + iv * gv;
            float hv = ov * tanh_fast(c[r]);
            hn[r * HID + t] = hv;
        }
        __syncthreads();

        // pred = h_new @ W_out^T + b_out  (56 threads; overlaps next step's GEMM)
        if (po < OUT_DIM) {
            const float4* hr = reinterpret_cast<const float4*>(hn + pr * HID);
            const float4* wr = s_wout + po * 33;
            float pa = 0.0f;
#pragma unroll 8
            for (int kk = 0; kk < 32; kk++) {
                float4 hv = hr[kk];
                float4 wv = wr[kk];
                pa += hv.x * wv.x + hv.y * wv.y + hv.z * wv.z + hv.w * wv.w;
            }
            out_base[(size_t)s * OUT_DIM] = pa + bpred;
        }
        cur ^= 1;
    }
}

extern "C" void kernel_launch(void* const* d_in, const int* in_sizes, int n_in,
                              void* d_out, int out_size) {
    const float* ctx  = (const float*)d_in[0];  // (1024,256,128)
    const float* Wih  = (const float*)d_in[1];  // (512,128)
    const float* Whh  = (const float*)d_in[2];  // (512,128)
    const float* bih  = (const float*)d_in[3];  // (512,)
    const float* bhh  = (const float*)d_in[4];  // (512,)
    const float* Wout = (const float*)d_in[5];  // (7,128)
    const float* bout = (const float*)d_in[6];  // (7,)
    float* out = (float*)d_out;                 // (1024,512,7)

    cudaFuncSetAttribute(lstm_kernel, cudaFuncAttributeMaxDynamicSharedMemorySize, SMEM_BYTES);

    prep_kernel<<<64, 256>>>(Wih, Whh, bih, bhh);
    lstm_kernel<<<NBLOCKS, TPB, SMEM_BYTES>>>(ctx, Wout, bout, out);
}